// round 9
// baseline (speedup 1.0000x reference)
#include <cuda_runtime.h>
#include <stdint.h>

// PackBits: word w has bit p = signbit(x[32*w + (p^7)])
//   (numpy packbits MSB-first per byte + little-endian uint32 view
//    => element k lands at bit position k^7 within its word.)
// Harness readback: reference uint32 words reinterpreted as SIGNED int32,
// value-compared -> store (float)(int32)word.
//
// R9: software ping-pong pipeline. Each warp walks a grid-stride sequence of
// 16-word tiles with two register buffers: tile i+1's 16 LDGs are issued
// BEFORE tile i's ballots run, so the warp always has loads in flight and the
// DRAM queue never drains during the vote/store phase (R8's duty-cycle gap:
// DRAM stuck at 84.7% while issue=27%).

#define WPW 16  // words per tile (per warp-iteration)

__global__ __launch_bounds__(256) void packbits_kernel(
    const unsigned int* __restrict__ x,  // fp32 bits: sign = bit 31
    float* __restrict__ out,
    int nwords, long long nelem)
{
    const int lane = threadIdx.x & 31;
    const int src_lane = lane ^ 7;
    const long long warp = (long long)((blockIdx.x * blockDim.x + threadIdx.x) >> 5);
    const long long nwarps = ((long long)gridDim.x * blockDim.x) >> 5;

    // Tiles that are fully in-bounds on both words and elements.
    long long full_tiles = (long long)nwords / WPW;
    long long elem_tiles = nelem / (32 * WPW);
    if (elem_tiles < full_tiles) full_tiles = elem_tiles;

    long long t = warp;
    if (t < full_tiles) {
        // Prefetch first tile.
        unsigned int a[WPW];
        {
            const unsigned int* p = x + t * (32 * WPW) + src_lane;
#pragma unroll
            for (int j = 0; j < WPW; j++) a[j] = __ldcs(p + j * 32);
        }

        for (;;) {
            const long long tn = t + nwarps;
            const bool more = (tn < full_tiles);

            // Issue next tile's loads before consuming current tile.
            unsigned int b[WPW];
            if (more) {
                const unsigned int* q = x + tn * (32 * WPW) + src_lane;
#pragma unroll
                for (int j = 0; j < WPW; j++) b[j] = __ldcs(q + j * 32);
            }

            // Ballot + store current tile (16 consecutive words, lanes 0..15).
            unsigned int mine = 0;
#pragma unroll
            for (int j = 0; j < WPW; j++) {
                unsigned int w = __ballot_sync(0xFFFFFFFFu, (int)a[j] < 0);
                if (lane == j) mine = w;
            }
            if (lane < WPW)
                __stcs(&out[t * WPW + lane], (float)(int)mine);

            if (!more) break;
#pragma unroll
            for (int j = 0; j < WPW; j++) a[j] = b[j];
            t = tn;
        }
    }

    // Tail words (none for N=2^27; generic correctness). Warp 0 of block 0.
    if (blockIdx.x == 0 && (threadIdx.x >> 5) == 0) {
        for (long long wi = full_tiles * WPW; wi < nwords; wi++) {
            long long idx = wi * 32 + src_lane;
            unsigned int v = (idx < nelem) ? x[idx] : 0u;
            unsigned int w = __ballot_sync(0xFFFFFFFFu, (int)v < 0);
            if (lane == 0) out[wi] = (float)(int)w;
        }
    }
}

extern "C" void kernel_launch(void* const* d_in, const int* in_sizes, int n_in,
                              void* d_out, int out_size)
{
    const unsigned int* x = (const unsigned int*)d_in[0];
    float* out = (float*)d_out;
    long long n = (long long)in_sizes[0];
    int nwords = out_size;  // ceil(n/32); here n = 2^27 -> nwords = 2^22

    // 2048 blocks x 8 warps = 16384 warps; 262144 tiles -> 16 tiles/warp,
    // enough pipeline depth to amortize the prefetch prologue.
    const int threads = 256;
    const int blocks = 2048;

    packbits_kernel<<<blocks, threads>>>(x, out, nwords, n);
}